// round 1
// baseline (speedup 1.0000x reference)
#include <cuda_runtime.h>

// Problem constants (B=1 fixed)
#define D_   24
#define H_   96
#define W_   96
#define C_   32
#define HW_  (H_*W_)          // 9216
#define S_   (D_*HW_)         // 221184
#define TOT_ (C_*S_)          // 7077888
#define OC_  54               // offset conv output channels (27 taps * 2)
#define G_   4
#define CPG_ (C_/G_)          // 8
#define NPG_ (CPG_*S_)        // 1769472 elements per group
#define STAT_BLOCKS 64

// Scratch (device globals: allocation-free, graph-capture safe)
__device__ float g_h[TOT_];          // gn+relu output (shared by both passes)
__device__ float g_t[TOT_];          // pass-1 deform output
__device__ float g_offb[OC_*S_];     // offset conv output
__device__ float g_part[G_*STAT_BLOCKS*2];
__device__ float g_ms[G_*2];         // per-group {mean, rstd}

// ---------------------------------------------------------------------------
// GroupNorm: two-level deterministic reduction. Group g's data is the
// contiguous range [g*NPG_, (g+1)*NPG_) since channels are grouped.
// ---------------------------------------------------------------------------
__global__ void gn_stats(const float* __restrict__ in) {
    int g = blockIdx.y;
    const float4* p = (const float4*)(in + (size_t)g * NPG_);
    const int n4 = NPG_ / 4;
    float s = 0.f, q = 0.f;
    for (int i = blockIdx.x * blockDim.x + threadIdx.x; i < n4; i += STAT_BLOCKS * 256) {
        float4 v = p[i];
        s += v.x + v.y + v.z + v.w;
        q += v.x*v.x + v.y*v.y + v.z*v.z + v.w*v.w;
    }
    __shared__ float sh[512];
    int t = threadIdx.x;
    sh[t] = s; sh[256 + t] = q;
    __syncthreads();
    for (int o = 128; o > 0; o >>= 1) {
        if (t < o) { sh[t] += sh[t + o]; sh[256 + t] += sh[256 + t + o]; }
        __syncthreads();
    }
    if (t == 0) {
        g_part[(g*STAT_BLOCKS + blockIdx.x)*2 + 0] = sh[0];
        g_part[(g*STAT_BLOCKS + blockIdx.x)*2 + 1] = sh[256];
    }
}

__global__ void gn_fin() {
    int g = blockIdx.x, t = threadIdx.x;
    __shared__ float a[64], b[64];
    a[t] = g_part[(g*STAT_BLOCKS + t)*2 + 0];
    b[t] = g_part[(g*STAT_BLOCKS + t)*2 + 1];
    __syncthreads();
    for (int o = 32; o > 0; o >>= 1) {
        if (t < o) { a[t] += a[t + o]; b[t] += b[t + o]; }
        __syncthreads();
    }
    if (t == 0) {
        float mean = a[0] / (float)NPG_;
        float var  = b[0] / (float)NPG_ - mean * mean;
        g_ms[g*2 + 0] = mean;
        g_ms[g*2 + 1] = rsqrtf(var + 1e-5f);
    }
}

__global__ void gn_apply(const float* __restrict__ in, const float* __restrict__ gamma,
                         const float* __restrict__ beta, float* __restrict__ out) {
    int i4 = blockIdx.x * blockDim.x + threadIdx.x;     // < TOT_/4
    int c  = i4 / (S_ / 4);
    int g  = c >> 3;
    float mean = g_ms[g*2 + 0], rstd = g_ms[g*2 + 1];
    float sc = rstd * gamma[c];
    float sb = beta[c] - mean * sc;
    float4 v = ((const float4*)in)[i4];
    float4 r;
    r.x = fmaxf(fmaf(v.x, sc, sb), 0.f);
    r.y = fmaxf(fmaf(v.y, sc, sb), 0.f);
    r.z = fmaxf(fmaf(v.z, sc, sb), 0.f);
    r.w = fmaxf(fmaf(v.w, sc, sb), 0.f);
    ((float4*)out)[i4] = r;
}

// ---------------------------------------------------------------------------
// Offset conv: 3x3x3, pad 1, 32 -> 54 channels.
// One thread = one voxel, all 54 outputs in registers (56 padded for float4).
// Per-tap weight slab in smem, broadcast LDS.128.
// ---------------------------------------------------------------------------
__global__ void __launch_bounds__(256)
conv_off(const float* __restrict__ in, const float* __restrict__ wt,
         const float* __restrict__ bias, float* __restrict__ out) {
    __shared__ float ws[C_ * 56];
    int sp = blockIdx.x * 256 + threadIdx.x;
    int d = sp / HW_;
    int r = sp - d * HW_;
    int h = r / W_;
    int w = r - h * W_;

    float acc[56];
    #pragma unroll
    for (int i = 0; i < 56; i++) acc[i] = 0.f;

    for (int tap = 0; tap < 27; ++tap) {
        __syncthreads();
        for (int idx = threadIdx.x; idx < C_ * 56; idx += 256) {
            int c = idx / 56, oc = idx - c * 56;
            ws[idx] = (oc < OC_) ? wt[(oc * C_ + c) * 27 + tap] : 0.f;
        }
        __syncthreads();
        int di = tap / 9 - 1;
        int dj = (tap / 3) % 3 - 1;
        int dk = tap % 3 - 1;
        int zd = d + di, zh = h + dj, zw = w + dk;
        if ((unsigned)zd < D_ && (unsigned)zh < H_ && (unsigned)zw < W_) {
            const float* ip = in + (zd * H_ + zh) * W_ + zw;
            #pragma unroll 4
            for (int c = 0; c < C_; c++) {
                float v = __ldg(ip + c * S_);
                const float4* wr = (const float4*)(ws + c * 56);
                #pragma unroll
                for (int q2 = 0; q2 < 14; q2++) {
                    float4 wv = wr[q2];
                    acc[4*q2 + 0] = fmaf(wv.x, v, acc[4*q2 + 0]);
                    acc[4*q2 + 1] = fmaf(wv.y, v, acc[4*q2 + 1]);
                    acc[4*q2 + 2] = fmaf(wv.z, v, acc[4*q2 + 2]);
                    acc[4*q2 + 3] = fmaf(wv.w, v, acc[4*q2 + 3]);
                }
            }
        }
    }
    #pragma unroll
    for (int oc = 0; oc < OC_; ++oc)
        out[oc * S_ + sp] = acc[oc] + bias[oc];
}

// ---------------------------------------------------------------------------
// Deformable conv (HW offsets, rigid depth taps with zero pad in D).
// One thread = one voxel, 32 output channels in registers.
// ---------------------------------------------------------------------------
__global__ void __launch_bounds__(256)
deform(const float* __restrict__ in, const float* __restrict__ offs,
       const float* __restrict__ wt, const float* __restrict__ bias,
       const float* __restrict__ resid, float* __restrict__ out) {
    __shared__ float ws[C_ * C_];
    int sp = blockIdx.x * 256 + threadIdx.x;
    int d = sp / HW_;              // uniform across block (HW_ % 256 == 0)
    int r = sp - d * HW_;
    int h = r / W_;
    int w = r - h * W_;

    float acc[C_];
    #pragma unroll
    for (int i = 0; i < C_; i++) acc[i] = 0.f;

    for (int tap = 0; tap < 27; ++tap) {
        __syncthreads();
        for (int idx = threadIdx.x; idx < C_ * C_; idx += 256) {
            int c = idx >> 5, oc = idx & 31;
            ws[idx] = wt[(oc * C_ + c) * 27 + tap];
        }
        __syncthreads();
        int zd = d + tap / 9 - 1;
        if ((unsigned)zd >= D_) continue;   // uniform per block: safe w.r.t. syncs

        float offh = offs[(2*tap + 0) * S_ + sp];
        float offw = offs[(2*tap + 1) * S_ + sp];
        float hp = (float)(h + (tap/3) % 3 - 1) + offh;
        float wp = (float)(w + tap % 3 - 1) + offw;
        float h0f = floorf(hp), w0f = floorf(wp);
        int h0 = (int)h0f, w0 = (int)w0f;
        float lh = hp - h0f, lw = wp - w0f;

        float m00 = ((unsigned)h0     < H_ && (unsigned)w0     < W_) ? 1.f : 0.f;
        float m01 = ((unsigned)h0     < H_ && (unsigned)(w0+1) < W_) ? 1.f : 0.f;
        float m10 = ((unsigned)(h0+1) < H_ && (unsigned)w0     < W_) ? 1.f : 0.f;
        float m11 = ((unsigned)(h0+1) < H_ && (unsigned)(w0+1) < W_) ? 1.f : 0.f;
        float w00 = (1.f - lh) * (1.f - lw) * m00;
        float w01 = (1.f - lh) * lw         * m01;
        float w10 = lh         * (1.f - lw) * m10;
        float w11 = lh         * lw         * m11;

        int h0c = min(max(h0,     0), H_ - 1);
        int h1c = min(max(h0 + 1, 0), H_ - 1);
        int w0c = min(max(w0,     0), W_ - 1);
        int w1c = min(max(w0 + 1, 0), W_ - 1);
        const float* base = in + zd * HW_;
        int i00 = h0c * W_ + w0c;
        int i01 = h0c * W_ + w1c;
        int i10 = h1c * W_ + w0c;
        int i11 = h1c * W_ + w1c;

        #pragma unroll 4
        for (int c = 0; c < C_; c++) {
            const float* pc = base + c * S_;
            float val = w00 * __ldg(pc + i00) + w01 * __ldg(pc + i01)
                      + w10 * __ldg(pc + i10) + w11 * __ldg(pc + i11);
            const float4* wr = (const float4*)(ws + c * C_);
            #pragma unroll
            for (int q2 = 0; q2 < 8; q2++) {
                float4 wv = wr[q2];
                acc[4*q2 + 0] = fmaf(wv.x, val, acc[4*q2 + 0]);
                acc[4*q2 + 1] = fmaf(wv.y, val, acc[4*q2 + 1]);
                acc[4*q2 + 2] = fmaf(wv.z, val, acc[4*q2 + 2]);
                acc[4*q2 + 3] = fmaf(wv.w, val, acc[4*q2 + 3]);
            }
        }
    }

    if (resid) {
        #pragma unroll
        for (int oc = 0; oc < C_; ++oc)
            out[oc * S_ + sp] = acc[oc] + bias[oc] + resid[oc * S_ + sp];
    } else {
        #pragma unroll
        for (int oc = 0; oc < C_; ++oc)
            out[oc * S_ + sp] = acc[oc] + bias[oc];
    }
}

// ---------------------------------------------------------------------------
extern "C" void kernel_launch(void* const* d_in, const int* in_sizes, int n_in,
                              void* d_out, int out_size) {
    const float* x   = (const float*)d_in[0];
    const float* g1  = (const float*)d_in[1];
    const float* be1 = (const float*)d_in[2];
    const float* g2  = (const float*)d_in[3];
    const float* be2 = (const float*)d_in[4];
    const float* ow1 = (const float*)d_in[5];
    const float* ob1 = (const float*)d_in[6];
    const float* dw1 = (const float*)d_in[7];
    const float* db1 = (const float*)d_in[8];
    const float* ow2 = (const float*)d_in[9];
    const float* ob2 = (const float*)d_in[10];
    const float* dw2 = (const float*)d_in[11];
    const float* db2 = (const float*)d_in[12];
    float* out = (float*)d_out;

    float *ph, *pt, *poff;
    cudaGetSymbolAddress((void**)&ph,   g_h);
    cudaGetSymbolAddress((void**)&pt,   g_t);
    cudaGetSymbolAddress((void**)&poff, g_offb);

    dim3 sg(STAT_BLOCKS, G_);
    const int NB_GN = TOT_ / 4 / 256;   // 6912
    const int NB_SP = S_ / 256;         // 864

    // pass 1
    gn_stats<<<sg, 256>>>(x);
    gn_fin<<<G_, 64>>>();
    gn_apply<<<NB_GN, 256>>>(x, g1, be1, ph);
    conv_off<<<NB_SP, 256>>>(ph, ow1, ob1, poff);
    deform<<<NB_SP, 256>>>(ph, poff, dw1, db1, nullptr, pt);

    // pass 2 (+ residual into d_out)
    gn_stats<<<sg, 256>>>(pt);
    gn_fin<<<G_, 64>>>();
    gn_apply<<<NB_GN, 256>>>(pt, g2, be2, ph);
    conv_off<<<NB_SP, 256>>>(ph, ow2, ob2, poff);
    deform<<<NB_SP, 256>>>(ph, poff, dw2, db2, x, out);
}